// round 11
// baseline (speedup 1.0000x reference)
#include <cuda_runtime.h>
#include <cuda_bf16.h>
#include <math.h>

typedef unsigned long long ull;
typedef unsigned int u32;

#define N0_DOCS 10000
#define MAXN1 50000
#define MAXN2 30000
#define NTOT (MAXN1 + MAXN2 + 2 * N0_DOCS)
#define ETOT (800000 + 480000 + 320000 + 160000)

// ---------------- feature scratch ----------------
__device__ u32   g_l1_1[MAXN1 * 64];
__device__ u32   g_l2_1[MAXN1 * 64];
__device__ u32   g_l1_2[MAXN2 * 64];
__device__ u32   g_l2_2[MAXN2 * 64];
__device__ float g_h1  [MAXN1 * 128];
__device__ float g_h2  [MAXN2 * 128];
__device__ float g_r0 [N0_DOCS * 128];
__device__ float g_r0s[N0_DOCS * 128];
__device__ float g_rA [N0_DOCS * 128];
__device__ float g_rB [N0_DOCS * 128];
__device__ float g_rw [N0_DOCS * 128];

// ---------------- CSR scratch ----------------
__device__ int   g_cntfc[2 * NTOT];
__device__ int   g_ptr[NTOT];
__device__ int   g_ci[ETOT];
__device__ float g_wv[ETOT];
__device__ int   g_bsum[128];

// ---------------------------------------------------------------------------
// helpers
// ---------------------------------------------------------------------------
__device__ __forceinline__ u32 smem_u32(const void* p) {
    u32 a;
    asm("{ .reg .u64 t; cvta.to.shared.u64 t, %1; cvt.u32.u64 %0, t; }"
        : "=r"(a) : "l"(p));
    return a;
}
__device__ __forceinline__ u32 pack_bf2(float a, float b) {
    u32 r;
    asm("cvt.rn.bf16x2.f32 %0, %1, %2;" : "=r"(r) : "f"(b), "f"(a));
    return r;
}
__device__ __forceinline__ float bf_to_f(u32 lo16) {
    return __uint_as_float(lo16 << 16);
}
__device__ __forceinline__ float2 bf2f(u32 p) {
    float2 r;
    r.x = __uint_as_float(p << 16);
    r.y = __uint_as_float(p & 0xFFFF0000u);
    return r;
}

#define LDM4(r, addr)                                                          \
    asm volatile("ldmatrix.sync.aligned.m8n8.x4.shared.b16 {%0,%1,%2,%3}, [%4];" \
                 : "=r"((r)[0]), "=r"((r)[1]), "=r"((r)[2]), "=r"((r)[3])      \
                 : "r"(addr))

#define MMA16816(c, a, b0v, b1v)                                               \
    asm volatile("mma.sync.aligned.m16n8k16.row.col.f32.bf16.bf16.f32 "        \
                 "{%0,%1,%2,%3}, {%4,%5,%6,%7}, {%8,%9}, {%0,%1,%2,%3};"       \
                 : "+f"((c)[0]), "+f"((c)[1]), "+f"((c)[2]), "+f"((c)[3])      \
                 : "r"((a)[0]), "r"((a)[1]), "r"((a)[2]), "r"((a)[3]),         \
                   "r"(b0v), "r"(b1v))

#define GEMM_STAGE 10240
#define GEMM_BUF   (4 * GEMM_STAGE)
#define GEMM_SMEM  (2 * GEMM_BUF)

// ===========================================================================
// Pipelined mma.sync bf16 hi/lo GEMM + bias + ReLU, bf16x2 output.
// ===========================================================================
__global__ __launch_bounds__(256) void gemm_mma_kernel(
    const float* __restrict__ A, const float* __restrict__ W,
    const float* __restrict__ bias, u32* __restrict__ Cb,
    int M, int K)
{
    extern __shared__ __align__(16) unsigned char smbuf[];
    const u32 sb = smem_u32(smbuf);

    const int tid  = threadIdx.x;
    const int lane = tid & 31, wid = tid >> 5;
    const int wm = wid & 3, wn = wid >> 2;
    const int lr = lane & 7, sub = lane >> 3;
    const int row0 = blockIdx.x * 128;

    const int arow = tid >> 1, akh = (tid & 1) * 16;
    const int bn   = tid & 127, bkh = (tid >> 7) * 16;
    const int gr   = row0 + arow;

    float acc[2][8][4];
#pragma unroll
    for (int i = 0; i < 2; i++)
#pragma unroll
        for (int j = 0; j < 8; j++)
#pragma unroll
            for (int c = 0; c < 4; c++) acc[i][j][c] = 0.f;

    const u32 a_off = (u32)((wm * 32 + lr + (sub & 1) * 8) * 80 + (sub >> 1) * 16);
    const u32 b_off = (u32)((wn * 64 + lr + (sub >> 1) * 8) * 80 + (sub & 1) * 16);

    float4 aR[4];
    float  bR[16];
    {
        const float* ap = A + (size_t)gr * K + akh;
#pragma unroll
        for (int q = 0; q < 4; q++)
            aR[q] = (gr < M) ? *(const float4*)(ap + q * 4)
                             : make_float4(0.f, 0.f, 0.f, 0.f);
        const float* wp = W + (size_t)bkh * 128 + bn;
#pragma unroll
        for (int q = 0; q < 16; q++) bR[q] = __ldg(wp + q * 128);
    }

    const int niter = K >> 5;
    for (int it = 0; it < niter; it++) {
        const u32 base = sb + (u32)(it & 1) * GEMM_BUF;
        const u32 AHI = base, ALO = base + GEMM_STAGE;
        const u32 BHI = base + 2 * GEMM_STAGE, BLO = base + 3 * GEMM_STAGE;

        {
            const u32 dh = AHI + arow * 80 + akh * 2;
            const u32 dl = ALO + arow * 80 + akh * 2;
#pragma unroll
            for (int q = 0; q < 4; q++) {
                float4 v = aR[q];
                u32 h0 = pack_bf2(v.x, v.y);
                u32 h1 = pack_bf2(v.z, v.w);
                float lx = v.x - bf_to_f(h0 & 0xFFFFu);
                float ly = v.y - bf_to_f(h0 >> 16);
                float lz = v.z - bf_to_f(h1 & 0xFFFFu);
                float lw = v.w - bf_to_f(h1 >> 16);
                u32 l0 = pack_bf2(lx, ly);
                u32 l1 = pack_bf2(lz, lw);
                asm volatile("st.shared.v2.b32 [%0], {%1,%2};"
                             :: "r"(dh + q * 8), "r"(h0), "r"(h1));
                asm volatile("st.shared.v2.b32 [%0], {%1,%2};"
                             :: "r"(dl + q * 8), "r"(l0), "r"(l1));
            }
            const u32 dbh = BHI + bn * 80 + bkh * 2;
            const u32 dbl = BLO + bn * 80 + bkh * 2;
#pragma unroll
            for (int q = 0; q < 4; q++) {
                float w0 = bR[4 * q + 0], w1 = bR[4 * q + 1];
                float w2 = bR[4 * q + 2], w3 = bR[4 * q + 3];
                u32 h0 = pack_bf2(w0, w1);
                u32 h1 = pack_bf2(w2, w3);
                float l0f = w0 - bf_to_f(h0 & 0xFFFFu);
                float l1f = w1 - bf_to_f(h0 >> 16);
                float l2f = w2 - bf_to_f(h1 & 0xFFFFu);
                float l3f = w3 - bf_to_f(h1 >> 16);
                u32 l0 = pack_bf2(l0f, l1f);
                u32 l1 = pack_bf2(l2f, l3f);
                asm volatile("st.shared.v2.b32 [%0], {%1,%2};"
                             :: "r"(dbh + q * 8), "r"(h0), "r"(h1));
                asm volatile("st.shared.v2.b32 [%0], {%1,%2};"
                             :: "r"(dbl + q * 8), "r"(l0), "r"(l1));
            }
        }
        __syncthreads();

        if (it + 1 < niter) {
            const int k0 = (it + 1) * 32;
            const float* ap = A + (size_t)gr * K + k0 + akh;
#pragma unroll
            for (int q = 0; q < 4; q++)
                aR[q] = (gr < M) ? *(const float4*)(ap + q * 4)
                                 : make_float4(0.f, 0.f, 0.f, 0.f);
            const float* wp = W + (size_t)(k0 + bkh) * 128 + bn;
#pragma unroll
            for (int q = 0; q < 16; q++) bR[q] = __ldg(wp + q * 128);
        }

#pragma unroll
        for (int j = 0; j < 2; j++) {
            u32 ah[2][4], al[2][4];
#pragma unroll
            for (int i = 0; i < 2; i++) {
                const u32 ro = a_off + i * 16 * 80 + j * 32;
                LDM4(ah[i], AHI + ro);
                LDM4(al[i], ALO + ro);
            }
#pragma unroll
            for (int p = 0; p < 4; p++) {
                const u32 bo = b_off + p * 16 * 80 + j * 32;
                u32 bh[4], bl[4];
                LDM4(bh, BHI + bo);
                LDM4(bl, BLO + bo);
                MMA16816(acc[0][2 * p],     ah[0], bh[0], bh[1]);
                MMA16816(acc[1][2 * p],     ah[1], bh[0], bh[1]);
                MMA16816(acc[0][2 * p + 1], ah[0], bh[2], bh[3]);
                MMA16816(acc[1][2 * p + 1], ah[1], bh[2], bh[3]);
                MMA16816(acc[0][2 * p],     ah[0], bl[0], bl[1]);
                MMA16816(acc[1][2 * p],     ah[1], bl[0], bl[1]);
                MMA16816(acc[0][2 * p + 1], ah[0], bl[2], bl[3]);
                MMA16816(acc[1][2 * p + 1], ah[1], bl[2], bl[3]);
                MMA16816(acc[0][2 * p],     al[0], bh[0], bh[1]);
                MMA16816(acc[1][2 * p],     al[1], bh[0], bh[1]);
                MMA16816(acc[0][2 * p + 1], al[0], bh[2], bh[3]);
                MMA16816(acc[1][2 * p + 1], al[1], bh[2], bh[3]);
            }
        }
    }

    const int gid = lane >> 2, tig = lane & 3;
#pragma unroll
    for (int i = 0; i < 2; i++) {
        const int ra = row0 + wm * 32 + i * 16 + gid;
        const int rb = ra + 8;
#pragma unroll
        for (int j8 = 0; j8 < 8; j8++) {
            const int col = wn * 64 + j8 * 8 + tig * 2;
            float b0 = __ldg(&bias[col]);
            float b1 = __ldg(&bias[col + 1]);
            float oa0 = fmaxf(acc[i][j8][0] + b0, 0.f);
            float oa1 = fmaxf(acc[i][j8][1] + b1, 0.f);
            float ob0 = fmaxf(acc[i][j8][2] + b0, 0.f);
            float ob1 = fmaxf(acc[i][j8][3] + b1, 0.f);
            if (ra < M) Cb[(size_t)ra * 64 + (col >> 1)] = pack_bf2(oa0, oa1);
            if (rb < M) Cb[(size_t)rb * 64 + (col >> 1)] = pack_bf2(ob0, ob1);
        }
    }
}

// ===========================================================================
// Fused CSR build
// ===========================================================================
__global__ __launch_bounds__(256) void hist_all_kernel(
    const int* __restrict__ d11, const int* __restrict__ d22,
    const int* __restrict__ d01, const int* __restrict__ d02,
    int E11, int E22, int E01, int E02,
    int b22, int b01, int b02,
    int* __restrict__ cnt)
{
    int i = blockIdx.x * blockDim.x + threadIdx.x;
    int E12 = E11 + E22, E123 = E12 + E01, E = E123 + E02;
    if (i >= E) return;
    int node;
    if (i < E11)       node =        d11[i];
    else if (i < E12)  node = b22 +  d22[i - E11];
    else if (i < E123) node = b01 +  d01[i - E12];
    else               node = b02 +  d02[i - E123];
    atomicAdd(&cnt[node], 1);
}

#define SCB 1024
__global__ __launch_bounds__(SCB) void scan1_kernel(
    const int* __restrict__ in, int* __restrict__ out, int* __restrict__ bsum, int n)
{
    __shared__ int sh[SCB];
    int i = blockIdx.x * SCB + threadIdx.x;
    int v = (i < n) ? in[i] : 0;
    sh[threadIdx.x] = v;
    __syncthreads();
#pragma unroll
    for (int o = 1; o < SCB; o <<= 1) {
        int t = (threadIdx.x >= o) ? sh[threadIdx.x - o] : 0;
        __syncthreads();
        sh[threadIdx.x] += t;
        __syncthreads();
    }
    if (i < n) out[i] = sh[threadIdx.x] - v;
    if (threadIdx.x == SCB - 1) bsum[blockIdx.x] = sh[threadIdx.x];
}

__global__ __launch_bounds__(SCB) void scan2_kernel(int* __restrict__ bsum, int nb)
{
    __shared__ int sh[SCB];
    int v = (threadIdx.x < nb) ? bsum[threadIdx.x] : 0;
    sh[threadIdx.x] = v;
    __syncthreads();
#pragma unroll
    for (int o = 1; o < SCB; o <<= 1) {
        int t = (threadIdx.x >= o) ? sh[threadIdx.x - o] : 0;
        __syncthreads();
        sh[threadIdx.x] += t;
        __syncthreads();
    }
    if (threadIdx.x < nb) bsum[threadIdx.x] = sh[threadIdx.x] - v;
}

__global__ __launch_bounds__(SCB) void scan3_kernel(
    int* __restrict__ out, const int* __restrict__ bsum, int n)
{
    int i = blockIdx.x * SCB + threadIdx.x;
    if (i < n) out[i] += bsum[blockIdx.x];
}

__global__ __launch_bounds__(256) void fill_all_kernel(
    const int* __restrict__ s11, const int* __restrict__ d11, const float* __restrict__ w11,
    const int* __restrict__ s22, const int* __restrict__ d22, const float* __restrict__ w22,
    const int* __restrict__ s01, const int* __restrict__ d01, const float* __restrict__ w01,
    const int* __restrict__ s02, const int* __restrict__ d02, const float* __restrict__ w02,
    int E11, int E22, int E01, int E02,
    int b22, int b01, int b02,
    const int* __restrict__ ptr, int* __restrict__ fc,
    int* __restrict__ ci, float* __restrict__ wv)
{
    int i = blockIdx.x * blockDim.x + threadIdx.x;
    int E12 = E11 + E22, E123 = E12 + E01, E = E123 + E02;
    if (i >= E) return;
    int node, s; float w;
    if (i < E11)       { node =       d11[i];        s = s11[i];        w = w11[i]; }
    else if (i < E12)  { int j = i - E11;  node = b22 + d22[j]; s = s22[j]; w = w22[j]; }
    else if (i < E123) { int j = i - E12;  node = b01 + d01[j]; s = s01[j]; w = w01[j]; }
    else               { int j = i - E123; node = b02 + d02[j]; s = s02[j]; w = w02[j]; }
    int pos = ptr[node] + atomicAdd(&fc[node], 1);
    ci[pos] = s;
    wv[pos] = w;
}

// ===========================================================================
// Gather kernels
// ===========================================================================
__device__ __forceinline__ void acc_bf2(float4& a, uint2 u, float w) {
    float2 p0 = bf2f(u.x), p1 = bf2f(u.y);
    a.x = fmaf(w, p0.x, a.x);
    a.y = fmaf(w, p0.y, a.y);
    a.z = fmaf(w, p1.x, a.z);
    a.w = fmaf(w, p1.y, a.w);
}

// bf16 features -> fp32 out
__global__ __launch_bounds__(256) void gather1_kernel(
    const int* __restrict__ ptr, const int* __restrict__ cnt,
    const int* __restrict__ ci, const float* __restrict__ wv,
    const u32* __restrict__ x, float* __restrict__ out, int N)
{
    int t = blockIdx.x * blockDim.x + threadIdx.x;
    int n = t >> 5;
    if (n >= N) return;
    int lane = t & 31;

    int beg = __ldg(&ptr[n]);
    int end = beg + __ldg(&cnt[n]);
    float4 acc = make_float4(0.f, 0.f, 0.f, 0.f);

    int e = beg;
    for (; e + 4 <= end; e += 4) {
        int s0 = __ldg(&ci[e]),   s1 = __ldg(&ci[e+1]);
        int s2 = __ldg(&ci[e+2]), s3 = __ldg(&ci[e+3]);
        float w0 = __ldg(&wv[e]),   w1 = __ldg(&wv[e+1]);
        float w2 = __ldg(&wv[e+2]), w3 = __ldg(&wv[e+3]);
        uint2 v0 = *(const uint2*)&x[(size_t)s0 * 64 + lane * 2];
        uint2 v1 = *(const uint2*)&x[(size_t)s1 * 64 + lane * 2];
        uint2 v2 = *(const uint2*)&x[(size_t)s2 * 64 + lane * 2];
        uint2 v3 = *(const uint2*)&x[(size_t)s3 * 64 + lane * 2];
        acc_bf2(acc, v0, w0);
        acc_bf2(acc, v1, w1);
        acc_bf2(acc, v2, w2);
        acc_bf2(acc, v3, w3);
    }
    for (; e < end; e++) {
        int s = __ldg(&ci[e]);
        float w0 = __ldg(&wv[e]);
        uint2 v = *(const uint2*)&x[(size_t)s * 64 + lane * 2];
        acc_bf2(acc, v, w0);
    }
    *(float4*)&out[(size_t)n * 128 + lane * 4] = acc;
}

// fp32 features -> fp32 out (for word_emb)
__global__ __launch_bounds__(256) void gather1f_kernel(
    const int* __restrict__ ptr, const int* __restrict__ cnt,
    const int* __restrict__ ci, const float* __restrict__ wv,
    const float* __restrict__ x, float* __restrict__ out, int N)
{
    int t = blockIdx.x * blockDim.x + threadIdx.x;
    int n = t >> 5;
    if (n >= N) return;
    int lane = t & 31;

    int beg = __ldg(&ptr[n]);
    int end = beg + __ldg(&cnt[n]);
    float4 acc = make_float4(0.f, 0.f, 0.f, 0.f);

    int e = beg;
    for (; e + 4 <= end; e += 4) {
        int s0 = __ldg(&ci[e]),   s1 = __ldg(&ci[e+1]);
        int s2 = __ldg(&ci[e+2]), s3 = __ldg(&ci[e+3]);
        float w0 = __ldg(&wv[e]),   w1 = __ldg(&wv[e+1]);
        float w2 = __ldg(&wv[e+2]), w3 = __ldg(&wv[e+3]);
        float4 v0 = *(const float4*)&x[(size_t)s0 * 128 + lane * 4];
        float4 v1 = *(const float4*)&x[(size_t)s1 * 128 + lane * 4];
        float4 v2 = *(const float4*)&x[(size_t)s2 * 128 + lane * 4];
        float4 v3 = *(const float4*)&x[(size_t)s3 * 128 + lane * 4];
        acc.x = fmaf(w0, v0.x, fmaf(w1, v1.x, fmaf(w2, v2.x, fmaf(w3, v3.x, acc.x))));
        acc.y = fmaf(w0, v0.y, fmaf(w1, v1.y, fmaf(w2, v2.y, fmaf(w3, v3.y, acc.y))));
        acc.z = fmaf(w0, v0.z, fmaf(w1, v1.z, fmaf(w2, v2.z, fmaf(w3, v3.z, acc.z))));
        acc.w = fmaf(w0, v0.w, fmaf(w1, v1.w, fmaf(w2, v2.w, fmaf(w3, v3.w, acc.w))));
    }
    for (; e < end; e++) {
        int s = __ldg(&ci[e]);
        float w0 = __ldg(&wv[e]);
        float4 v = *(const float4*)&x[(size_t)s * 128 + lane * 4];
        acc.x = fmaf(w0, v.x, acc.x);
        acc.y = fmaf(w0, v.y, acc.y);
        acc.z = fmaf(w0, v.z, acc.z);
        acc.w = fmaf(w0, v.w, acc.w);
    }
    *(float4*)&out[(size_t)n * 128 + lane * 4] = acc;
}

// ===========================================================================
// Finalize
// ===========================================================================
__global__ __launch_bounds__(128) void finalize_kernel(
    const float* __restrict__ r0, const float* __restrict__ rA,
    const float* __restrict__ rw, const float* __restrict__ r0s,
    const float* __restrict__ rB, float* __restrict__ out)
{
    const int n = blockIdx.x;
    const int t = threadIdx.x;
    const int lane = t & 31, wid = t >> 5;

    const size_t base = (size_t)n * 128 + t;
    float v0  = r0 [base];
    float vA  = rA [base];
    float vW  = rw [base];
    float v0s = r0s[base];
    float vB  = rB [base];

    float4 sq = make_float4(v0 * v0, vA * vA + vW * vW,
                            v0s * v0s, vB * vB + vW * vW);
#pragma unroll
    for (int o = 16; o; o >>= 1) {
        sq.x += __shfl_xor_sync(0xffffffffu, sq.x, o);
        sq.y += __shfl_xor_sync(0xffffffffu, sq.y, o);
        sq.z += __shfl_xor_sync(0xffffffffu, sq.z, o);
        sq.w += __shfl_xor_sync(0xffffffffu, sq.w, o);
    }
    __shared__ float4 wsum[4];
    if (lane == 0) wsum[wid] = sq;
    __syncthreads();
    float s0  = wsum[0].x + wsum[1].x + wsum[2].x + wsum[3].x;
    float s1  = wsum[0].y + wsum[1].y + wsum[2].y + wsum[3].y;
    float s0s = wsum[0].z + wsum[1].z + wsum[2].z + wsum[3].z;
    float s1s = wsum[0].w + wsum[1].w + wsum[2].w + wsum[3].w;

    const float EPS = 1e-9f;
    float i0  = 1.f / (sqrtf(s0)  + EPS);
    float i1  = 1.f / (sqrtf(s1)  + EPS);
    float i0s = 1.f / (sqrtf(s0s) + EPS);
    float i1s = 1.f / (sqrtf(s1s) + EPS);

    size_t drow = (size_t)n * 384;
    out[drow + t]       = v0 * i0;
    out[drow + 128 + t] = vA * i1;
    out[drow + 256 + t] = vW * i1;

    size_t srow = (size_t)N0_DOCS * 384 + drow;
    out[srow + t]       = v0s * i0s;
    out[srow + 128 + t] = vB * i1s;
    out[srow + 256 + t] = vW * i1s;
}

// ===========================================================================
// Launch — host enqueue order chosen so every cudaStreamWaitEvent follows
// its cudaEventRecord (stream-capture requirement).
// ===========================================================================
extern "C" void kernel_launch(void* const* d_in, const int* in_sizes, int n_in,
                              void* d_out, int out_size)
{
    const float* x1       = (const float*)d_in[0];
    const float* x2       = (const float*)d_in[1];
    const float* word_emb = (const float*)d_in[2];
    const float* W1a = (const float*)d_in[3];
    const float* b1a = (const float*)d_in[4];
    const float* W1b = (const float*)d_in[5];
    const float* b1b = (const float*)d_in[6];
    const float* W2a = (const float*)d_in[7];
    const float* b2a = (const float*)d_in[8];
    const float* W2b = (const float*)d_in[9];
    const float* b2b = (const float*)d_in[10];
    const int*   e11_src = (const int*)d_in[11];
    const int*   e11_dst = (const int*)d_in[12];
    const float* e11_w   = (const float*)d_in[13];
    const int*   e22_src = (const int*)d_in[14];
    const int*   e22_dst = (const int*)d_in[15];
    const float* e22_w   = (const float*)d_in[16];
    const int*   e01_src = (const int*)d_in[17];
    const int*   e01_dst = (const int*)d_in[18];
    const float* e01_w   = (const float*)d_in[19];
    const int*   e02_src = (const int*)d_in[20];
    const int*   e02_dst = (const int*)d_in[21];
    const float* e02_w   = (const float*)d_in[22];

    const int N1  = in_sizes[0] / 256;
    const int N2  = in_sizes[1] / 256;
    const int E11 = in_sizes[11];
    const int E22 = in_sizes[14];
    const int E01 = in_sizes[17];
    const int E02 = in_sizes[20];
    const int Etot = E11 + E22 + E01 + E02;
    const int Ntot = N1 + N2 + 2 * N0_DOCS;
    const int b22 = N1, b01 = N1 + N2, b02 = N1 + N2 + N0_DOCS;

    u32 *l1_1, *l2_1, *l1_2, *l2_2;
    float *h1, *h2, *r0, *r0s, *rA, *rB, *rw;
    cudaGetSymbolAddress((void**)&l1_1, g_l1_1);
    cudaGetSymbolAddress((void**)&l2_1, g_l2_1);
    cudaGetSymbolAddress((void**)&l1_2, g_l1_2);
    cudaGetSymbolAddress((void**)&l2_2, g_l2_2);
    cudaGetSymbolAddress((void**)&h1,   g_h1);
    cudaGetSymbolAddress((void**)&h2,   g_h2);
    cudaGetSymbolAddress((void**)&r0,   g_r0);
    cudaGetSymbolAddress((void**)&r0s,  g_r0s);
    cudaGetSymbolAddress((void**)&rA,   g_rA);
    cudaGetSymbolAddress((void**)&rB,   g_rB);
    cudaGetSymbolAddress((void**)&rw,   g_rw);

    int *cntfc, *ptr, *ci, *bsum;
    float *wv;
    cudaGetSymbolAddress((void**)&cntfc, g_cntfc);
    cudaGetSymbolAddress((void**)&ptr,   g_ptr);
    cudaGetSymbolAddress((void**)&ci,    g_ci);
    cudaGetSymbolAddress((void**)&wv,    g_wv);
    cudaGetSymbolAddress((void**)&bsum,  g_bsum);
    int* cnt = cntfc;
    int* fc  = cntfc + NTOT;

    static cudaStream_t s1 = nullptr, s2 = nullptr, s3 = nullptr;
    static cudaEvent_t ev0 = nullptr, ev1 = nullptr, ev2 = nullptr, ev3 = nullptr;
    static cudaEvent_t ecsr = nullptr, eg1 = nullptr, eg2 = nullptr;
    if (s1 == nullptr) {
        cudaStreamCreateWithFlags(&s1, cudaStreamNonBlocking);
        cudaStreamCreateWithFlags(&s2, cudaStreamNonBlocking);
        cudaStreamCreateWithFlags(&s3, cudaStreamNonBlocking);
        cudaEventCreateWithFlags(&ev0, cudaEventDisableTiming);
        cudaEventCreateWithFlags(&ev1, cudaEventDisableTiming);
        cudaEventCreateWithFlags(&ev2, cudaEventDisableTiming);
        cudaEventCreateWithFlags(&ev3, cudaEventDisableTiming);
        cudaEventCreateWithFlags(&ecsr, cudaEventDisableTiming);
        cudaEventCreateWithFlags(&eg1, cudaEventDisableTiming);
        cudaEventCreateWithFlags(&eg2, cudaEventDisableTiming);
        cudaFuncSetAttribute(gemm_mma_kernel,
                             cudaFuncAttributeMaxDynamicSharedMemorySize, GEMM_SMEM);
    }

    const unsigned gdoc = (N0_DOCS * 32 + 255) / 256;

    // Fork
    cudaEventRecord(ev0, 0);
    cudaStreamWaitEvent(s1, ev0, 0);
    cudaStreamWaitEvent(s2, ev0, 0);
    cudaStreamWaitEvent(s3, ev0, 0);

    // ---- Phase A: first GEMMs (records eg1/eg2 before anyone waits) ----
    gemm_mma_kernel<<<(N1 + 127) / 128, 256, GEMM_SMEM, s1>>>(
        x1, W1a, b1a, l1_1, N1, 256);
    cudaEventRecord(eg1, s1);
    gemm_mma_kernel<<<(N2 + 127) / 128, 256, GEMM_SMEM, s2>>>(
        x2, W2a, b2a, l1_2, N2, 256);
    cudaEventRecord(eg2, s2);

    // ---- Phase B: stream 3 — CSR build, then slack-filling doc gathers ----
    cudaMemsetAsync(cntfc, 0, 2 * NTOT * sizeof(int), s3);
    hist_all_kernel<<<(Etot + 255) / 256, 256, 0, s3>>>(
        e11_dst, e22_dst, e01_dst, e02_dst, E11, E22, E01, E02,
        b22, b01, b02, cnt);
    int nb = (Ntot + SCB - 1) / SCB;
    scan1_kernel<<<nb, SCB, 0, s3>>>(cnt, ptr, bsum, Ntot);
    scan2_kernel<<<1, SCB, 0, s3>>>(bsum, nb);
    scan3_kernel<<<nb, SCB, 0, s3>>>(ptr, bsum, Ntot);
    fill_all_kernel<<<(Etot + 255) / 256, 256, 0, s3>>>(
        e11_src, e11_dst, e11_w, e22_src, e22_dst, e22_w,
        e01_src, e01_dst, e01_w, e02_src, e02_dst, e02_w,
        E11, E22, E01, E02, b22, b01, b02, ptr, fc, ci, wv);
    cudaEventRecord(ecsr, s3);
    // rw: depends only on CSR + word_emb input
    gather1f_kernel<<<gdoc, 256, 0, s3>>>(
        ptr + b02, cnt + b02, ci, wv, word_emb, rw, N0_DOCS);
    // r0s: needs l1_1 (eg1 already recorded)
    cudaStreamWaitEvent(s3, eg1, 0);
    gather1_kernel<<<gdoc, 256, 0, s3>>>(
        ptr + b01, cnt + b01, ci, wv, l1_1, r0s, N0_DOCS);
    // rB: needs l1_2 (eg2 already recorded)
    cudaStreamWaitEvent(s3, eg2, 0);
    gather1_kernel<<<gdoc, 256, 0, s3>>>(
        ptr + b02, cnt + b02, ci, wv, l1_2, rB, N0_DOCS);
    cudaEventRecord(ev3, s3);

    // ---- Phase C: rest of stream 1 (critical path, single-output tail) ----
    cudaStreamWaitEvent(s1, ecsr, 0);
    gather1_kernel<<<(N1 * 32 + 255) / 256, 256, 0, s1>>>(
        ptr, cnt, ci, wv, l1_1, h1, N1);
    gemm_mma_kernel<<<(N1 + 127) / 128, 256, GEMM_SMEM, s1>>>(
        h1, W1b, b1b, l2_1, N1, 128);
    gather1_kernel<<<gdoc, 256, 0, s1>>>(
        ptr + b01, cnt + b01, ci, wv, l2_1, r0, N0_DOCS);
    cudaEventRecord(ev1, s1);

    // ---- Phase D: rest of stream 2 ----
    cudaStreamWaitEvent(s2, ecsr, 0);
    gather1_kernel<<<(N2 * 32 + 255) / 256, 256, 0, s2>>>(
        ptr + b22, cnt + b22, ci, wv, l1_2, h2, N2);
    gemm_mma_kernel<<<(N2 + 127) / 128, 256, GEMM_SMEM, s2>>>(
        h2, W2b, b2b, l2_2, N2, 128);
    gather1_kernel<<<gdoc, 256, 0, s2>>>(
        ptr + b02, cnt + b02, ci, wv, l2_2, rA, N0_DOCS);
    cudaEventRecord(ev2, s2);

    // ---- join + finalize ----
    cudaStreamWaitEvent(0, ev1, 0);
    cudaStreamWaitEvent(0, ev2, 0);
    cudaStreamWaitEvent(0, ev3, 0);
    finalize_kernel<<<N0_DOCS, 128, 0, 0>>>(r0, rA, rw, r0s, rB, (float*)d_out);
}

// round 12
// speedup vs baseline: 1.0342x; 1.0342x over previous
#include <cuda_runtime.h>
#include <cuda_bf16.h>
#include <math.h>

typedef unsigned long long ull;
typedef unsigned int u32;

#define N0_DOCS 10000
#define MAXN1 50000
#define MAXN2 30000
#define NTOT (MAXN1 + MAXN2 + 2 * N0_DOCS)
#define ETOT (800000 + 480000 + 320000 + 160000)

// ---------------- feature scratch ----------------
__device__ u32   g_l1_1[MAXN1 * 64];
__device__ u32   g_l2_1[MAXN1 * 64];
__device__ u32   g_l1_2[MAXN2 * 64];
__device__ u32   g_l2_2[MAXN2 * 64];
__device__ float g_h1  [MAXN1 * 128];
__device__ float g_h2  [MAXN2 * 128];
__device__ float g_r0 [N0_DOCS * 128];
__device__ float g_r0s[N0_DOCS * 128];
__device__ float g_rA [N0_DOCS * 128];
__device__ float g_rB [N0_DOCS * 128];
__device__ float g_rw [N0_DOCS * 128];

// ---------------- CSR scratch ----------------
__device__ int   g_cntfc[2 * NTOT];
__device__ int   g_ptr[NTOT];
__device__ int   g_ci[ETOT];
__device__ float g_wv[ETOT];
__device__ int   g_bsum[128];

// ---------------------------------------------------------------------------
// helpers
// ---------------------------------------------------------------------------
__device__ __forceinline__ u32 smem_u32(const void* p) {
    u32 a;
    asm("{ .reg .u64 t; cvta.to.shared.u64 t, %1; cvt.u32.u64 %0, t; }"
        : "=r"(a) : "l"(p));
    return a;
}
__device__ __forceinline__ u32 pack_bf2(float a, float b) {
    u32 r;
    asm("cvt.rn.bf16x2.f32 %0, %1, %2;" : "=r"(r) : "f"(b), "f"(a));
    return r;
}
__device__ __forceinline__ float bf_to_f(u32 lo16) {
    return __uint_as_float(lo16 << 16);
}
__device__ __forceinline__ float2 bf2f(u32 p) {
    float2 r;
    r.x = __uint_as_float(p << 16);
    r.y = __uint_as_float(p & 0xFFFF0000u);
    return r;
}

#define LDM4(r, addr)                                                          \
    asm volatile("ldmatrix.sync.aligned.m8n8.x4.shared.b16 {%0,%1,%2,%3}, [%4];" \
                 : "=r"((r)[0]), "=r"((r)[1]), "=r"((r)[2]), "=r"((r)[3])      \
                 : "r"(addr))

#define MMA16816(c, a, b0v, b1v)                                               \
    asm volatile("mma.sync.aligned.m16n8k16.row.col.f32.bf16.bf16.f32 "        \
                 "{%0,%1,%2,%3}, {%4,%5,%6,%7}, {%8,%9}, {%0,%1,%2,%3};"       \
                 : "+f"((c)[0]), "+f"((c)[1]), "+f"((c)[2]), "+f"((c)[3])      \
                 : "r"((a)[0]), "r"((a)[1]), "r"((a)[2]), "r"((a)[3]),         \
                   "r"(b0v), "r"(b1v))

#define GEMM_STAGE 10240
#define GEMM_BUF   (4 * GEMM_STAGE)
#define GEMM_SMEM  (2 * GEMM_BUF)

// ===========================================================================
// Pipelined mma.sync bf16 hi/lo GEMM + bias + ReLU, bf16x2 output.
// ===========================================================================
__global__ __launch_bounds__(256) void gemm_mma_kernel(
    const float* __restrict__ A, const float* __restrict__ W,
    const float* __restrict__ bias, u32* __restrict__ Cb,
    int M, int K)
{
    extern __shared__ __align__(16) unsigned char smbuf[];
    const u32 sb = smem_u32(smbuf);

    const int tid  = threadIdx.x;
    const int lane = tid & 31, wid = tid >> 5;
    const int wm = wid & 3, wn = wid >> 2;
    const int lr = lane & 7, sub = lane >> 3;
    const int row0 = blockIdx.x * 128;

    const int arow = tid >> 1, akh = (tid & 1) * 16;
    const int bn   = tid & 127, bkh = (tid >> 7) * 16;
    const int gr   = row0 + arow;

    float acc[2][8][4];
#pragma unroll
    for (int i = 0; i < 2; i++)
#pragma unroll
        for (int j = 0; j < 8; j++)
#pragma unroll
            for (int c = 0; c < 4; c++) acc[i][j][c] = 0.f;

    const u32 a_off = (u32)((wm * 32 + lr + (sub & 1) * 8) * 80 + (sub >> 1) * 16);
    const u32 b_off = (u32)((wn * 64 + lr + (sub >> 1) * 8) * 80 + (sub & 1) * 16);

    float4 aR[4];
    float  bR[16];
    {
        const float* ap = A + (size_t)gr * K + akh;
#pragma unroll
        for (int q = 0; q < 4; q++)
            aR[q] = (gr < M) ? *(const float4*)(ap + q * 4)
                             : make_float4(0.f, 0.f, 0.f, 0.f);
        const float* wp = W + (size_t)bkh * 128 + bn;
#pragma unroll
        for (int q = 0; q < 16; q++) bR[q] = __ldg(wp + q * 128);
    }

    const int niter = K >> 5;
    for (int it = 0; it < niter; it++) {
        const u32 base = sb + (u32)(it & 1) * GEMM_BUF;
        const u32 AHI = base, ALO = base + GEMM_STAGE;
        const u32 BHI = base + 2 * GEMM_STAGE, BLO = base + 3 * GEMM_STAGE;

        {
            const u32 dh = AHI + arow * 80 + akh * 2;
            const u32 dl = ALO + arow * 80 + akh * 2;
#pragma unroll
            for (int q = 0; q < 4; q++) {
                float4 v = aR[q];
                u32 h0 = pack_bf2(v.x, v.y);
                u32 h1 = pack_bf2(v.z, v.w);
                float lx = v.x - bf_to_f(h0 & 0xFFFFu);
                float ly = v.y - bf_to_f(h0 >> 16);
                float lz = v.z - bf_to_f(h1 & 0xFFFFu);
                float lw = v.w - bf_to_f(h1 >> 16);
                u32 l0 = pack_bf2(lx, ly);
                u32 l1 = pack_bf2(lz, lw);
                asm volatile("st.shared.v2.b32 [%0], {%1,%2};"
                             :: "r"(dh + q * 8), "r"(h0), "r"(h1));
                asm volatile("st.shared.v2.b32 [%0], {%1,%2};"
                             :: "r"(dl + q * 8), "r"(l0), "r"(l1));
            }
            const u32 dbh = BHI + bn * 80 + bkh * 2;
            const u32 dbl = BLO + bn * 80 + bkh * 2;
#pragma unroll
            for (int q = 0; q < 4; q++) {
                float w0 = bR[4 * q + 0], w1 = bR[4 * q + 1];
                float w2 = bR[4 * q + 2], w3 = bR[4 * q + 3];
                u32 h0 = pack_bf2(w0, w1);
                u32 h1 = pack_bf2(w2, w3);
                float l0f = w0 - bf_to_f(h0 & 0xFFFFu);
                float l1f = w1 - bf_to_f(h0 >> 16);
                float l2f = w2 - bf_to_f(h1 & 0xFFFFu);
                float l3f = w3 - bf_to_f(h1 >> 16);
                u32 l0 = pack_bf2(l0f, l1f);
                u32 l1 = pack_bf2(l2f, l3f);
                asm volatile("st.shared.v2.b32 [%0], {%1,%2};"
                             :: "r"(dbh + q * 8), "r"(h0), "r"(h1));
                asm volatile("st.shared.v2.b32 [%0], {%1,%2};"
                             :: "r"(dbl + q * 8), "r"(l0), "r"(l1));
            }
        }
        __syncthreads();

        if (it + 1 < niter) {
            const int k0 = (it + 1) * 32;
            const float* ap = A + (size_t)gr * K + k0 + akh;
#pragma unroll
            for (int q = 0; q < 4; q++)
                aR[q] = (gr < M) ? *(const float4*)(ap + q * 4)
                                 : make_float4(0.f, 0.f, 0.f, 0.f);
            const float* wp = W + (size_t)(k0 + bkh) * 128 + bn;
#pragma unroll
            for (int q = 0; q < 16; q++) bR[q] = __ldg(wp + q * 128);
        }

#pragma unroll
        for (int j = 0; j < 2; j++) {
            u32 ah[2][4], al[2][4];
#pragma unroll
            for (int i = 0; i < 2; i++) {
                const u32 ro = a_off + i * 16 * 80 + j * 32;
                LDM4(ah[i], AHI + ro);
                LDM4(al[i], ALO + ro);
            }
#pragma unroll
            for (int p = 0; p < 4; p++) {
                const u32 bo = b_off + p * 16 * 80 + j * 32;
                u32 bh[4], bl[4];
                LDM4(bh, BHI + bo);
                LDM4(bl, BLO + bo);
                MMA16816(acc[0][2 * p],     ah[0], bh[0], bh[1]);
                MMA16816(acc[1][2 * p],     ah[1], bh[0], bh[1]);
                MMA16816(acc[0][2 * p + 1], ah[0], bh[2], bh[3]);
                MMA16816(acc[1][2 * p + 1], ah[1], bh[2], bh[3]);
                MMA16816(acc[0][2 * p],     ah[0], bl[0], bl[1]);
                MMA16816(acc[1][2 * p],     ah[1], bl[0], bl[1]);
                MMA16816(acc[0][2 * p + 1], ah[0], bl[2], bl[3]);
                MMA16816(acc[1][2 * p + 1], ah[1], bl[2], bl[3]);
                MMA16816(acc[0][2 * p],     al[0], bh[0], bh[1]);
                MMA16816(acc[1][2 * p],     al[1], bh[0], bh[1]);
                MMA16816(acc[0][2 * p + 1], al[0], bh[2], bh[3]);
                MMA16816(acc[1][2 * p + 1], al[1], bh[2], bh[3]);
            }
        }
    }

    const int gid = lane >> 2, tig = lane & 3;
#pragma unroll
    for (int i = 0; i < 2; i++) {
        const int ra = row0 + wm * 32 + i * 16 + gid;
        const int rb = ra + 8;
#pragma unroll
        for (int j8 = 0; j8 < 8; j8++) {
            const int col = wn * 64 + j8 * 8 + tig * 2;
            float b0 = __ldg(&bias[col]);
            float b1 = __ldg(&bias[col + 1]);
            float oa0 = fmaxf(acc[i][j8][0] + b0, 0.f);
            float oa1 = fmaxf(acc[i][j8][1] + b1, 0.f);
            float ob0 = fmaxf(acc[i][j8][2] + b0, 0.f);
            float ob1 = fmaxf(acc[i][j8][3] + b1, 0.f);
            if (ra < M) Cb[(size_t)ra * 64 + (col >> 1)] = pack_bf2(oa0, oa1);
            if (rb < M) Cb[(size_t)rb * 64 + (col >> 1)] = pack_bf2(ob0, ob1);
        }
    }
}

// ===========================================================================
// Fused CSR build
// ===========================================================================
__global__ __launch_bounds__(256) void hist_all_kernel(
    const int* __restrict__ d11, const int* __restrict__ d22,
    const int* __restrict__ d01, const int* __restrict__ d02,
    int E11, int E22, int E01, int E02,
    int b22, int b01, int b02,
    int* __restrict__ cnt)
{
    int i = blockIdx.x * blockDim.x + threadIdx.x;
    int E12 = E11 + E22, E123 = E12 + E01, E = E123 + E02;
    if (i >= E) return;
    int node;
    if (i < E11)       node =        d11[i];
    else if (i < E12)  node = b22 +  d22[i - E11];
    else if (i < E123) node = b01 +  d01[i - E12];
    else               node = b02 +  d02[i - E123];
    atomicAdd(&cnt[node], 1);
}

#define SCB 1024
__global__ __launch_bounds__(SCB) void scan1_kernel(
    const int* __restrict__ in, int* __restrict__ out, int* __restrict__ bsum, int n)
{
    __shared__ int sh[SCB];
    int i = blockIdx.x * SCB + threadIdx.x;
    int v = (i < n) ? in[i] : 0;
    sh[threadIdx.x] = v;
    __syncthreads();
#pragma unroll
    for (int o = 1; o < SCB; o <<= 1) {
        int t = (threadIdx.x >= o) ? sh[threadIdx.x - o] : 0;
        __syncthreads();
        sh[threadIdx.x] += t;
        __syncthreads();
    }
    if (i < n) out[i] = sh[threadIdx.x] - v;
    if (threadIdx.x == SCB - 1) bsum[blockIdx.x] = sh[threadIdx.x];
}

__global__ __launch_bounds__(SCB) void scan2_kernel(int* __restrict__ bsum, int nb)
{
    __shared__ int sh[SCB];
    int v = (threadIdx.x < nb) ? bsum[threadIdx.x] : 0;
    sh[threadIdx.x] = v;
    __syncthreads();
#pragma unroll
    for (int o = 1; o < SCB; o <<= 1) {
        int t = (threadIdx.x >= o) ? sh[threadIdx.x - o] : 0;
        __syncthreads();
        sh[threadIdx.x] += t;
        __syncthreads();
    }
    if (threadIdx.x < nb) bsum[threadIdx.x] = sh[threadIdx.x] - v;
}

__global__ __launch_bounds__(SCB) void scan3_kernel(
    int* __restrict__ out, const int* __restrict__ bsum, int n)
{
    int i = blockIdx.x * SCB + threadIdx.x;
    if (i < n) out[i] += bsum[blockIdx.x];
}

__global__ __launch_bounds__(256) void fill_all_kernel(
    const int* __restrict__ s11, const int* __restrict__ d11, const float* __restrict__ w11,
    const int* __restrict__ s22, const int* __restrict__ d22, const float* __restrict__ w22,
    const int* __restrict__ s01, const int* __restrict__ d01, const float* __restrict__ w01,
    const int* __restrict__ s02, const int* __restrict__ d02, const float* __restrict__ w02,
    int E11, int E22, int E01, int E02,
    int b22, int b01, int b02,
    const int* __restrict__ ptr, int* __restrict__ fc,
    int* __restrict__ ci, float* __restrict__ wv)
{
    int i = blockIdx.x * blockDim.x + threadIdx.x;
    int E12 = E11 + E22, E123 = E12 + E01, E = E123 + E02;
    if (i >= E) return;
    int node, s; float w;
    if (i < E11)       { node =       d11[i];        s = s11[i];        w = w11[i]; }
    else if (i < E12)  { int j = i - E11;  node = b22 + d22[j]; s = s22[j]; w = w22[j]; }
    else if (i < E123) { int j = i - E12;  node = b01 + d01[j]; s = s01[j]; w = w01[j]; }
    else               { int j = i - E123; node = b02 + d02[j]; s = s02[j]; w = w02[j]; }
    int pos = ptr[node] + atomicAdd(&fc[node], 1);
    ci[pos] = s;
    wv[pos] = w;
}

// ===========================================================================
// Gather SpMM kernels — bf16 feature reads, fp32 accumulate
// ===========================================================================
__device__ __forceinline__ void acc_bf2(float4& a, uint2 u, float w) {
    float2 p0 = bf2f(u.x), p1 = bf2f(u.y);
    a.x = fmaf(w, p0.x, a.x);
    a.y = fmaf(w, p0.y, a.y);
    a.z = fmaf(w, p1.x, a.z);
    a.w = fmaf(w, p1.y, a.w);
}

__global__ __launch_bounds__(256) void gather1_kernel(
    const int* __restrict__ ptr, const int* __restrict__ cnt,
    const int* __restrict__ ci, const float* __restrict__ wv,
    const u32* __restrict__ x, float* __restrict__ out, int N)
{
    int t = blockIdx.x * blockDim.x + threadIdx.x;
    int n = t >> 5;
    if (n >= N) return;
    int lane = t & 31;

    int beg = __ldg(&ptr[n]);
    int end = beg + __ldg(&cnt[n]);
    float4 acc = make_float4(0.f, 0.f, 0.f, 0.f);

    int e = beg;
    for (; e + 4 <= end; e += 4) {
        int s0 = __ldg(&ci[e]),   s1 = __ldg(&ci[e+1]);
        int s2 = __ldg(&ci[e+2]), s3 = __ldg(&ci[e+3]);
        float w0 = __ldg(&wv[e]),   w1 = __ldg(&wv[e+1]);
        float w2 = __ldg(&wv[e+2]), w3 = __ldg(&wv[e+3]);
        uint2 v0 = *(const uint2*)&x[(size_t)s0 * 64 + lane * 2];
        uint2 v1 = *(const uint2*)&x[(size_t)s1 * 64 + lane * 2];
        uint2 v2 = *(const uint2*)&x[(size_t)s2 * 64 + lane * 2];
        uint2 v3 = *(const uint2*)&x[(size_t)s3 * 64 + lane * 2];
        acc_bf2(acc, v0, w0);
        acc_bf2(acc, v1, w1);
        acc_bf2(acc, v2, w2);
        acc_bf2(acc, v3, w3);
    }
    for (; e < end; e++) {
        int s = __ldg(&ci[e]);
        float w0 = __ldg(&wv[e]);
        uint2 v = *(const uint2*)&x[(size_t)s * 64 + lane * 2];
        acc_bf2(acc, v, w0);
    }
    *(float4*)&out[(size_t)n * 128 + lane * 4] = acc;
}

// two bf16 features -> two fp32 outputs
__global__ __launch_bounds__(256) void gather2_kernel(
    const int* __restrict__ ptr, const int* __restrict__ cnt,
    const int* __restrict__ ci, const float* __restrict__ wv,
    const u32* __restrict__ x0, const u32* __restrict__ x1,
    float* __restrict__ o0, float* __restrict__ o1, int N)
{
    int t = blockIdx.x * blockDim.x + threadIdx.x;
    int n = t >> 5;
    if (n >= N) return;
    int lane = t & 31;

    int beg = __ldg(&ptr[n]);
    int end = beg + __ldg(&cnt[n]);
    float4 a0 = make_float4(0.f, 0.f, 0.f, 0.f);
    float4 a1 = a0;

    int e = beg;
    for (; e + 2 <= end; e += 2) {
        int sA = __ldg(&ci[e]), sB = __ldg(&ci[e+1]);
        float wA = __ldg(&wv[e]), wB = __ldg(&wv[e+1]);
        size_t oA = (size_t)sA * 64 + lane * 2;
        size_t oB = (size_t)sB * 64 + lane * 2;
        uint2 vA0 = *(const uint2*)&x0[oA];
        uint2 vB0 = *(const uint2*)&x0[oB];
        uint2 vA1 = *(const uint2*)&x1[oA];
        uint2 vB1 = *(const uint2*)&x1[oB];
        acc_bf2(a0, vA0, wA); acc_bf2(a0, vB0, wB);
        acc_bf2(a1, vA1, wA); acc_bf2(a1, vB1, wB);
    }
    for (; e < end; e++) {
        int s = __ldg(&ci[e]);
        float w0 = __ldg(&wv[e]);
        size_t o = (size_t)s * 64 + lane * 2;
        uint2 v0 = *(const uint2*)&x0[o];
        uint2 v1 = *(const uint2*)&x1[o];
        acc_bf2(a0, v0, w0);
        acc_bf2(a1, v1, w0);
    }
    size_t od = (size_t)n * 128 + lane * 4;
    *(float4*)&o0[od] = a0;
    *(float4*)&o1[od] = a1;
}

// fp32 features -> fp32 out (for word_emb)
__global__ __launch_bounds__(256) void gather1f_kernel(
    const int* __restrict__ ptr, const int* __restrict__ cnt,
    const int* __restrict__ ci, const float* __restrict__ wv,
    const float* __restrict__ x, float* __restrict__ out, int N)
{
    int t = blockIdx.x * blockDim.x + threadIdx.x;
    int n = t >> 5;
    if (n >= N) return;
    int lane = t & 31;

    int beg = __ldg(&ptr[n]);
    int end = beg + __ldg(&cnt[n]);
    float4 acc = make_float4(0.f, 0.f, 0.f, 0.f);

    int e = beg;
    for (; e + 4 <= end; e += 4) {
        int s0 = __ldg(&ci[e]),   s1 = __ldg(&ci[e+1]);
        int s2 = __ldg(&ci[e+2]), s3 = __ldg(&ci[e+3]);
        float w0 = __ldg(&wv[e]),   w1 = __ldg(&wv[e+1]);
        float w2 = __ldg(&wv[e+2]), w3 = __ldg(&wv[e+3]);
        float4 v0 = *(const float4*)&x[(size_t)s0 * 128 + lane * 4];
        float4 v1 = *(const float4*)&x[(size_t)s1 * 128 + lane * 4];
        float4 v2 = *(const float4*)&x[(size_t)s2 * 128 + lane * 4];
        float4 v3 = *(const float4*)&x[(size_t)s3 * 128 + lane * 4];
        acc.x = fmaf(w0, v0.x, fmaf(w1, v1.x, fmaf(w2, v2.x, fmaf(w3, v3.x, acc.x))));
        acc.y = fmaf(w0, v0.y, fmaf(w1, v1.y, fmaf(w2, v2.y, fmaf(w3, v3.y, acc.y))));
        acc.z = fmaf(w0, v0.z, fmaf(w1, v1.z, fmaf(w2, v2.z, fmaf(w3, v3.z, acc.z))));
        acc.w = fmaf(w0, v0.w, fmaf(w1, v1.w, fmaf(w2, v2.w, fmaf(w3, v3.w, acc.w))));
    }
    for (; e < end; e++) {
        int s = __ldg(&ci[e]);
        float w0 = __ldg(&wv[e]);
        float4 v = *(const float4*)&x[(size_t)s * 128 + lane * 4];
        acc.x = fmaf(w0, v.x, acc.x);
        acc.y = fmaf(w0, v.y, acc.y);
        acc.z = fmaf(w0, v.z, acc.z);
        acc.w = fmaf(w0, v.w, acc.w);
    }
    *(float4*)&out[(size_t)n * 128 + lane * 4] = acc;
}

// ===========================================================================
// Finalize
// ===========================================================================
__global__ __launch_bounds__(128) void finalize_kernel(
    const float* __restrict__ r0, const float* __restrict__ rA,
    const float* __restrict__ rw, const float* __restrict__ r0s,
    const float* __restrict__ rB, float* __restrict__ out)
{
    const int n = blockIdx.x;
    const int t = threadIdx.x;
    const int lane = t & 31, wid = t >> 5;

    const size_t base = (size_t)n * 128 + t;
    float v0  = r0 [base];
    float vA  = rA [base];
    float vW  = rw [base];
    float v0s = r0s[base];
    float vB  = rB [base];

    float4 sq = make_float4(v0 * v0, vA * vA + vW * vW,
                            v0s * v0s, vB * vB + vW * vW);
#pragma unroll
    for (int o = 16; o; o >>= 1) {
        sq.x += __shfl_xor_sync(0xffffffffu, sq.x, o);
        sq.y += __shfl_xor_sync(0xffffffffu, sq.y, o);
        sq.z += __shfl_xor_sync(0xffffffffu, sq.z, o);
        sq.w += __shfl_xor_sync(0xffffffffu, sq.w, o);
    }
    __shared__ float4 wsum[4];
    if (lane == 0) wsum[wid] = sq;
    __syncthreads();
    float s0  = wsum[0].x + wsum[1].x + wsum[2].x + wsum[3].x;
    float s1  = wsum[0].y + wsum[1].y + wsum[2].y + wsum[3].y;
    float s0s = wsum[0].z + wsum[1].z + wsum[2].z + wsum[3].z;
    float s1s = wsum[0].w + wsum[1].w + wsum[2].w + wsum[3].w;

    const float EPS = 1e-9f;
    float i0  = 1.f / (sqrtf(s0)  + EPS);
    float i1  = 1.f / (sqrtf(s1)  + EPS);
    float i0s = 1.f / (sqrtf(s0s) + EPS);
    float i1s = 1.f / (sqrtf(s1s) + EPS);

    size_t drow = (size_t)n * 384;
    out[drow + t]       = v0 * i0;
    out[drow + 128 + t] = vA * i1;
    out[drow + 256 + t] = vW * i1;

    size_t srow = (size_t)N0_DOCS * 384 + drow;
    out[srow + t]       = v0s * i0s;
    out[srow + 128 + t] = vB * i1s;
    out[srow + 256 + t] = vW * i1s;
}

// ===========================================================================
// Launch (round-8 topology; rw gather hoisted to s3 CSR-phase slack)
// ===========================================================================
extern "C" void kernel_launch(void* const* d_in, const int* in_sizes, int n_in,
                              void* d_out, int out_size)
{
    const float* x1       = (const float*)d_in[0];
    const float* x2       = (const float*)d_in[1];
    const float* word_emb = (const float*)d_in[2];
    const float* W1a = (const float*)d_in[3];
    const float* b1a = (const float*)d_in[4];
    const float* W1b = (const float*)d_in[5];
    const float* b1b = (const float*)d_in[6];
    const float* W2a = (const float*)d_in[7];
    const float* b2a = (const float*)d_in[8];
    const float* W2b = (const float*)d_in[9];
    const float* b2b = (const float*)d_in[10];
    const int*   e11_src = (const int*)d_in[11];
    const int*   e11_dst = (const int*)d_in[12];
    const float* e11_w   = (const float*)d_in[13];
    const int*   e22_src = (const int*)d_in[14];
    const int*   e22_dst = (const int*)d_in[15];
    const float* e22_w   = (const float*)d_in[16];
    const int*   e01_src = (const int*)d_in[17];
    const int*   e01_dst = (const int*)d_in[18];
    const float* e01_w   = (const float*)d_in[19];
    const int*   e02_src = (const int*)d_in[20];
    const int*   e02_dst = (const int*)d_in[21];
    const float* e02_w   = (const float*)d_in[22];

    const int N1  = in_sizes[0] / 256;
    const int N2  = in_sizes[1] / 256;
    const int E11 = in_sizes[11];
    const int E22 = in_sizes[14];
    const int E01 = in_sizes[17];
    const int E02 = in_sizes[20];
    const int Etot = E11 + E22 + E01 + E02;
    const int Ntot = N1 + N2 + 2 * N0_DOCS;
    const int b22 = N1, b01 = N1 + N2, b02 = N1 + N2 + N0_DOCS;

    u32 *l1_1, *l2_1, *l1_2, *l2_2;
    float *h1, *h2, *r0, *r0s, *rA, *rB, *rw;
    cudaGetSymbolAddress((void**)&l1_1, g_l1_1);
    cudaGetSymbolAddress((void**)&l2_1, g_l2_1);
    cudaGetSymbolAddress((void**)&l1_2, g_l1_2);
    cudaGetSymbolAddress((void**)&l2_2, g_l2_2);
    cudaGetSymbolAddress((void**)&h1,   g_h1);
    cudaGetSymbolAddress((void**)&h2,   g_h2);
    cudaGetSymbolAddress((void**)&r0,   g_r0);
    cudaGetSymbolAddress((void**)&r0s,  g_r0s);
    cudaGetSymbolAddress((void**)&rA,   g_rA);
    cudaGetSymbolAddress((void**)&rB,   g_rB);
    cudaGetSymbolAddress((void**)&rw,   g_rw);

    int *cntfc, *ptr, *ci, *bsum;
    float *wv;
    cudaGetSymbolAddress((void**)&cntfc, g_cntfc);
    cudaGetSymbolAddress((void**)&ptr,   g_ptr);
    cudaGetSymbolAddress((void**)&ci,    g_ci);
    cudaGetSymbolAddress((void**)&wv,    g_wv);
    cudaGetSymbolAddress((void**)&bsum,  g_bsum);
    int* cnt = cntfc;
    int* fc  = cntfc + NTOT;

    static cudaStream_t s1 = nullptr, s2 = nullptr, s3 = nullptr;
    static cudaEvent_t ev0 = nullptr, ev1 = nullptr, ev2 = nullptr, ev3 = nullptr;
    static cudaEvent_t ecsr = nullptr;
    if (s1 == nullptr) {
        cudaStreamCreateWithFlags(&s1, cudaStreamNonBlocking);
        cudaStreamCreateWithFlags(&s2, cudaStreamNonBlocking);
        cudaStreamCreateWithFlags(&s3, cudaStreamNonBlocking);
        cudaEventCreateWithFlags(&ev0, cudaEventDisableTiming);
        cudaEventCreateWithFlags(&ev1, cudaEventDisableTiming);
        cudaEventCreateWithFlags(&ev2, cudaEventDisableTiming);
        cudaEventCreateWithFlags(&ev3, cudaEventDisableTiming);
        cudaEventCreateWithFlags(&ecsr, cudaEventDisableTiming);
        cudaFuncSetAttribute(gemm_mma_kernel,
                             cudaFuncAttributeMaxDynamicSharedMemorySize, GEMM_SMEM);
    }

    const unsigned gdoc = (N0_DOCS * 32 + 255) / 256;

    // Fork
    cudaEventRecord(ev0, 0);
    cudaStreamWaitEvent(s1, ev0, 0);
    cudaStreamWaitEvent(s2, ev0, 0);
    cudaStreamWaitEvent(s3, ev0, 0);

    // ---- stream 3: fused CSR build + rw gather (input-only dependency) ----
    cudaMemsetAsync(cntfc, 0, 2 * NTOT * sizeof(int), s3);
    hist_all_kernel<<<(Etot + 255) / 256, 256, 0, s3>>>(
        e11_dst, e22_dst, e01_dst, e02_dst, E11, E22, E01, E02,
        b22, b01, b02, cnt);
    int nb = (Ntot + SCB - 1) / SCB;
    scan1_kernel<<<nb, SCB, 0, s3>>>(cnt, ptr, bsum, Ntot);
    scan2_kernel<<<1, SCB, 0, s3>>>(bsum, nb);
    scan3_kernel<<<nb, SCB, 0, s3>>>(ptr, bsum, Ntot);
    fill_all_kernel<<<(Etot + 255) / 256, 256, 0, s3>>>(
        e11_src, e11_dst, e11_w, e22_src, e22_dst, e22_w,
        e01_src, e01_dst, e01_w, e02_src, e02_dst, e02_w,
        E11, E22, E01, E02, b22, b01, b02, ptr, fc, ci, wv);
    cudaEventRecord(ecsr, s3);
    gather1f_kernel<<<gdoc, 256, 0, s3>>>(
        ptr + b02, cnt + b02, ci, wv, word_emb, rw, N0_DOCS);
    cudaEventRecord(ev3, s3);

    // ---- stream 1: type-1 pipeline ----
    gemm_mma_kernel<<<(N1 + 127) / 128, 256, GEMM_SMEM, s1>>>(
        x1, W1a, b1a, l1_1, N1, 256);
    cudaStreamWaitEvent(s1, ecsr, 0);
    gather1_kernel<<<(N1 * 32 + 255) / 256, 256, 0, s1>>>(
        ptr, cnt, ci, wv, l1_1, h1, N1);
    gemm_mma_kernel<<<(N1 + 127) / 128, 256, GEMM_SMEM, s1>>>(
        h1, W1b, b1b, l2_1, N1, 128);
    gather2_kernel<<<gdoc, 256, 0, s1>>>(
        ptr + b01, cnt + b01, ci, wv, l2_1, l1_1, r0, r0s, N0_DOCS);
    cudaEventRecord(ev1, s1);

    // ---- stream 2: type-2 pipeline ----
    gemm_mma_kernel<<<(N2 + 127) / 128, 256, GEMM_SMEM, s2>>>(
        x2, W2a, b2a, l1_2, N2, 256);
    cudaStreamWaitEvent(s2, ecsr, 0);
    gather1_kernel<<<(N2 * 32 + 255) / 256, 256, 0, s2>>>(
        ptr + b22, cnt + b22, ci, wv, l1_2, h2, N2);
    gemm_mma_kernel<<<(N2 + 127) / 128, 256, GEMM_SMEM, s2>>>(
        h2, W2b, b2b, l2_2, N2, 128);
    gather2_kernel<<<gdoc, 256, 0, s2>>>(
        ptr + b02, cnt + b02, ci, wv, l2_2, l1_2, rA, rB, N0_DOCS);
    cudaEventRecord(ev2, s2);

    // ---- join + finalize ----
    cudaStreamWaitEvent(0, ev1, 0);
    cudaStreamWaitEvent(0, ev2, 0);
    cudaStreamWaitEvent(0, ev3, 0);
    finalize_kernel<<<N0_DOCS, 128, 0, 0>>>(r0, rA, rw, r0s, rB, (float*)d_out);
}

// round 13
// speedup vs baseline: 1.0344x; 1.0001x over previous
#include <cuda_runtime.h>
#include <cuda_bf16.h>
#include <math.h>

typedef unsigned long long ull;
typedef unsigned int u32;

#define N0_DOCS 10000
#define MAXN1 50000
#define MAXN2 30000
#define NTOT (MAXN1 + MAXN2 + 2 * N0_DOCS)
#define ETOT (800000 + 480000 + 320000 + 160000)

// ---------------- feature scratch ----------------
__device__ u32   g_l1_1[MAXN1 * 64];
__device__ u32   g_l2_1[MAXN1 * 64];
__device__ u32   g_l1_2[MAXN2 * 64];
__device__ u32   g_l2_2[MAXN2 * 64];
__device__ float g_h1  [MAXN1 * 128];
__device__ float g_h2  [MAXN2 * 128];
__device__ float g_r0 [N0_DOCS * 128];
__device__ float g_r0s[N0_DOCS * 128];
__device__ float g_rA [N0_DOCS * 128];
__device__ float g_rB [N0_DOCS * 128];
__device__ float g_rw [N0_DOCS * 128];

// ---------------- CSR scratch ----------------
__device__ int   g_cntfc[2 * NTOT];
__device__ int   g_ptr[NTOT];
__device__ int   g_ci[ETOT];
__device__ float g_wv[ETOT];
__device__ int   g_bsum[128];

// ---------------------------------------------------------------------------
// helpers
// ---------------------------------------------------------------------------
__device__ __forceinline__ u32 smem_u32(const void* p) {
    u32 a;
    asm("{ .reg .u64 t; cvta.to.shared.u64 t, %1; cvt.u32.u64 %0, t; }"
        : "=r"(a) : "l"(p));
    return a;
}
__device__ __forceinline__ u32 pack_bf2(float a, float b) {
    u32 r;
    asm("cvt.rn.bf16x2.f32 %0, %1, %2;" : "=r"(r) : "f"(b), "f"(a));
    return r;
}
__device__ __forceinline__ float bf_to_f(u32 lo16) {
    return __uint_as_float(lo16 << 16);
}
__device__ __forceinline__ float2 bf2f(u32 p) {
    float2 r;
    r.x = __uint_as_float(p << 16);
    r.y = __uint_as_float(p & 0xFFFF0000u);
    return r;
}

#define LDM4(r, addr)                                                          \
    asm volatile("ldmatrix.sync.aligned.m8n8.x4.shared.b16 {%0,%1,%2,%3}, [%4];" \
                 : "=r"((r)[0]), "=r"((r)[1]), "=r"((r)[2]), "=r"((r)[3])      \
                 : "r"(addr))

#define MMA16816(c, a, b0v, b1v)                                               \
    asm volatile("mma.sync.aligned.m16n8k16.row.col.f32.bf16.bf16.f32 "        \
                 "{%0,%1,%2,%3}, {%4,%5,%6,%7}, {%8,%9}, {%0,%1,%2,%3};"       \
                 : "+f"((c)[0]), "+f"((c)[1]), "+f"((c)[2]), "+f"((c)[3])      \
                 : "r"((a)[0]), "r"((a)[1]), "r"((a)[2]), "r"((a)[3]),         \
                   "r"(b0v), "r"(b1v))

#define GEMM_STAGE 10240
#define GEMM_BUF   (4 * GEMM_STAGE)
#define GEMM_SMEM  (2 * GEMM_BUF)

// ===========================================================================
// Pipelined mma.sync bf16 hi/lo GEMM + bias + ReLU, bf16x2 output.
// ===========================================================================
__global__ __launch_bounds__(256) void gemm_mma_kernel(
    const float* __restrict__ A, const float* __restrict__ W,
    const float* __restrict__ bias, u32* __restrict__ Cb,
    int M, int K)
{
    extern __shared__ __align__(16) unsigned char smbuf[];
    const u32 sb = smem_u32(smbuf);

    const int tid  = threadIdx.x;
    const int lane = tid & 31, wid = tid >> 5;
    const int wm = wid & 3, wn = wid >> 2;
    const int lr = lane & 7, sub = lane >> 3;
    const int row0 = blockIdx.x * 128;

    const int arow = tid >> 1, akh = (tid & 1) * 16;
    const int bn   = tid & 127, bkh = (tid >> 7) * 16;
    const int gr   = row0 + arow;

    float acc[2][8][4];
#pragma unroll
    for (int i = 0; i < 2; i++)
#pragma unroll
        for (int j = 0; j < 8; j++)
#pragma unroll
            for (int c = 0; c < 4; c++) acc[i][j][c] = 0.f;

    const u32 a_off = (u32)((wm * 32 + lr + (sub & 1) * 8) * 80 + (sub >> 1) * 16);
    const u32 b_off = (u32)((wn * 64 + lr + (sub >> 1) * 8) * 80 + (sub & 1) * 16);

    float4 aR[4];
    float  bR[16];
    {
        const float* ap = A + (size_t)gr * K + akh;
#pragma unroll
        for (int q = 0; q < 4; q++)
            aR[q] = (gr < M) ? *(const float4*)(ap + q * 4)
                             : make_float4(0.f, 0.f, 0.f, 0.f);
        const float* wp = W + (size_t)bkh * 128 + bn;
#pragma unroll
        for (int q = 0; q < 16; q++) bR[q] = __ldg(wp + q * 128);
    }

    const int niter = K >> 5;
    for (int it = 0; it < niter; it++) {
        const u32 base = sb + (u32)(it & 1) * GEMM_BUF;
        const u32 AHI = base, ALO = base + GEMM_STAGE;
        const u32 BHI = base + 2 * GEMM_STAGE, BLO = base + 3 * GEMM_STAGE;

        {
            const u32 dh = AHI + arow * 80 + akh * 2;
            const u32 dl = ALO + arow * 80 + akh * 2;
#pragma unroll
            for (int q = 0; q < 4; q++) {
                float4 v = aR[q];
                u32 h0 = pack_bf2(v.x, v.y);
                u32 h1 = pack_bf2(v.z, v.w);
                float lx = v.x - bf_to_f(h0 & 0xFFFFu);
                float ly = v.y - bf_to_f(h0 >> 16);
                float lz = v.z - bf_to_f(h1 & 0xFFFFu);
                float lw = v.w - bf_to_f(h1 >> 16);
                u32 l0 = pack_bf2(lx, ly);
                u32 l1 = pack_bf2(lz, lw);
                asm volatile("st.shared.v2.b32 [%0], {%1,%2};"
                             :: "r"(dh + q * 8), "r"(h0), "r"(h1));
                asm volatile("st.shared.v2.b32 [%0], {%1,%2};"
                             :: "r"(dl + q * 8), "r"(l0), "r"(l1));
            }
            const u32 dbh = BHI + bn * 80 + bkh * 2;
            const u32 dbl = BLO + bn * 80 + bkh * 2;
#pragma unroll
            for (int q = 0; q < 4; q++) {
                float w0 = bR[4 * q + 0], w1 = bR[4 * q + 1];
                float w2 = bR[4 * q + 2], w3 = bR[4 * q + 3];
                u32 h0 = pack_bf2(w0, w1);
                u32 h1 = pack_bf2(w2, w3);
                float l0f = w0 - bf_to_f(h0 & 0xFFFFu);
                float l1f = w1 - bf_to_f(h0 >> 16);
                float l2f = w2 - bf_to_f(h1 & 0xFFFFu);
                float l3f = w3 - bf_to_f(h1 >> 16);
                u32 l0 = pack_bf2(l0f, l1f);
                u32 l1 = pack_bf2(l2f, l3f);
                asm volatile("st.shared.v2.b32 [%0], {%1,%2};"
                             :: "r"(dbh + q * 8), "r"(h0), "r"(h1));
                asm volatile("st.shared.v2.b32 [%0], {%1,%2};"
                             :: "r"(dbl + q * 8), "r"(l0), "r"(l1));
            }
        }
        __syncthreads();

        if (it + 1 < niter) {
            const int k0 = (it + 1) * 32;
            const float* ap = A + (size_t)gr * K + k0 + akh;
#pragma unroll
            for (int q = 0; q < 4; q++)
                aR[q] = (gr < M) ? *(const float4*)(ap + q * 4)
                                 : make_float4(0.f, 0.f, 0.f, 0.f);
            const float* wp = W + (size_t)(k0 + bkh) * 128 + bn;
#pragma unroll
            for (int q = 0; q < 16; q++) bR[q] = __ldg(wp + q * 128);
        }

#pragma unroll
        for (int j = 0; j < 2; j++) {
            u32 ah[2][4], al[2][4];
#pragma unroll
            for (int i = 0; i < 2; i++) {
                const u32 ro = a_off + i * 16 * 80 + j * 32;
                LDM4(ah[i], AHI + ro);
                LDM4(al[i], ALO + ro);
            }
#pragma unroll
            for (int p = 0; p < 4; p++) {
                const u32 bo = b_off + p * 16 * 80 + j * 32;
                u32 bh[4], bl[4];
                LDM4(bh, BHI + bo);
                LDM4(bl, BLO + bo);
                MMA16816(acc[0][2 * p],     ah[0], bh[0], bh[1]);
                MMA16816(acc[1][2 * p],     ah[1], bh[0], bh[1]);
                MMA16816(acc[0][2 * p + 1], ah[0], bh[2], bh[3]);
                MMA16816(acc[1][2 * p + 1], ah[1], bh[2], bh[3]);
                MMA16816(acc[0][2 * p],     ah[0], bl[0], bl[1]);
                MMA16816(acc[1][2 * p],     ah[1], bl[0], bl[1]);
                MMA16816(acc[0][2 * p + 1], ah[0], bl[2], bl[3]);
                MMA16816(acc[1][2 * p + 1], ah[1], bl[2], bl[3]);
                MMA16816(acc[0][2 * p],     al[0], bh[0], bh[1]);
                MMA16816(acc[1][2 * p],     al[1], bh[0], bh[1]);
                MMA16816(acc[0][2 * p + 1], al[0], bh[2], bh[3]);
                MMA16816(acc[1][2 * p + 1], al[1], bh[2], bh[3]);
            }
        }
    }

    const int gid = lane >> 2, tig = lane & 3;
#pragma unroll
    for (int i = 0; i < 2; i++) {
        const int ra = row0 + wm * 32 + i * 16 + gid;
        const int rb = ra + 8;
#pragma unroll
        for (int j8 = 0; j8 < 8; j8++) {
            const int col = wn * 64 + j8 * 8 + tig * 2;
            float b0 = __ldg(&bias[col]);
            float b1 = __ldg(&bias[col + 1]);
            float oa0 = fmaxf(acc[i][j8][0] + b0, 0.f);
            float oa1 = fmaxf(acc[i][j8][1] + b1, 0.f);
            float ob0 = fmaxf(acc[i][j8][2] + b0, 0.f);
            float ob1 = fmaxf(acc[i][j8][3] + b1, 0.f);
            if (ra < M) Cb[(size_t)ra * 64 + (col >> 1)] = pack_bf2(oa0, oa1);
            if (rb < M) Cb[(size_t)rb * 64 + (col >> 1)] = pack_bf2(ob0, ob1);
        }
    }
}

// ===========================================================================
// Fused CSR build
// ===========================================================================
__global__ __launch_bounds__(256) void hist_all_kernel(
    const int* __restrict__ d11, const int* __restrict__ d22,
    const int* __restrict__ d01, const int* __restrict__ d02,
    int E11, int E22, int E01, int E02,
    int b22, int b01, int b02,
    int* __restrict__ cnt)
{
    int i = blockIdx.x * blockDim.x + threadIdx.x;
    int E12 = E11 + E22, E123 = E12 + E01, E = E123 + E02;
    if (i >= E) return;
    int node;
    if (i < E11)       node =        d11[i];
    else if (i < E12)  node = b22 +  d22[i - E11];
    else if (i < E123) node = b01 +  d01[i - E12];
    else               node = b02 +  d02[i - E123];
    atomicAdd(&cnt[node], 1);
}

#define SCB 1024
__global__ __launch_bounds__(SCB) void scan1_kernel(
    const int* __restrict__ in, int* __restrict__ out, int* __restrict__ bsum, int n)
{
    __shared__ int sh[SCB];
    int i = blockIdx.x * SCB + threadIdx.x;
    int v = (i < n) ? in[i] : 0;
    sh[threadIdx.x] = v;
    __syncthreads();
#pragma unroll
    for (int o = 1; o < SCB; o <<= 1) {
        int t = (threadIdx.x >= o) ? sh[threadIdx.x - o] : 0;
        __syncthreads();
        sh[threadIdx.x] += t;
        __syncthreads();
    }
    if (i < n) out[i] = sh[threadIdx.x] - v;
    if (threadIdx.x == SCB - 1) bsum[blockIdx.x] = sh[threadIdx.x];
}

__global__ __launch_bounds__(SCB) void scan2_kernel(int* __restrict__ bsum, int nb)
{
    __shared__ int sh[SCB];
    int v = (threadIdx.x < nb) ? bsum[threadIdx.x] : 0;
    sh[threadIdx.x] = v;
    __syncthreads();
#pragma unroll
    for (int o = 1; o < SCB; o <<= 1) {
        int t = (threadIdx.x >= o) ? sh[threadIdx.x - o] : 0;
        __syncthreads();
        sh[threadIdx.x] += t;
        __syncthreads();
    }
    if (threadIdx.x < nb) bsum[threadIdx.x] = sh[threadIdx.x] - v;
}

__global__ __launch_bounds__(SCB) void scan3_kernel(
    int* __restrict__ out, const int* __restrict__ bsum, int n)
{
    int i = blockIdx.x * SCB + threadIdx.x;
    if (i < n) out[i] += bsum[blockIdx.x];
}

__global__ __launch_bounds__(256) void fill_all_kernel(
    const int* __restrict__ s11, const int* __restrict__ d11, const float* __restrict__ w11,
    const int* __restrict__ s22, const int* __restrict__ d22, const float* __restrict__ w22,
    const int* __restrict__ s01, const int* __restrict__ d01, const float* __restrict__ w01,
    const int* __restrict__ s02, const int* __restrict__ d02, const float* __restrict__ w02,
    int E11, int E22, int E01, int E02,
    int b22, int b01, int b02,
    const int* __restrict__ ptr, int* __restrict__ fc,
    int* __restrict__ ci, float* __restrict__ wv)
{
    int i = blockIdx.x * blockDim.x + threadIdx.x;
    int E12 = E11 + E22, E123 = E12 + E01, E = E123 + E02;
    if (i >= E) return;
    int node, s; float w;
    if (i < E11)       { node =       d11[i];        s = s11[i];        w = w11[i]; }
    else if (i < E12)  { int j = i - E11;  node = b22 + d22[j]; s = s22[j]; w = w22[j]; }
    else if (i < E123) { int j = i - E12;  node = b01 + d01[j]; s = s01[j]; w = w01[j]; }
    else               { int j = i - E123; node = b02 + d02[j]; s = s02[j]; w = w02[j]; }
    int pos = ptr[node] + atomicAdd(&fc[node], 1);
    ci[pos] = s;
    wv[pos] = w;
}

// ===========================================================================
// Gather SpMM kernels — bf16 feature reads, fp32 accumulate.
// Load/use phase separation for MLP=8.
// ===========================================================================
__device__ __forceinline__ void acc_bf2(float4& a, uint2 u, float w) {
    float2 p0 = bf2f(u.x), p1 = bf2f(u.y);
    a.x = fmaf(w, p0.x, a.x);
    a.y = fmaf(w, p0.y, a.y);
    a.z = fmaf(w, p1.x, a.z);
    a.w = fmaf(w, p1.y, a.w);
}

__global__ __launch_bounds__(256) void gather1_kernel(
    const int* __restrict__ ptr, const int* __restrict__ cnt,
    const int* __restrict__ ci, const float* __restrict__ wv,
    const u32* __restrict__ x, float* __restrict__ out, int N)
{
    int t = blockIdx.x * blockDim.x + threadIdx.x;
    int n = t >> 5;
    if (n >= N) return;
    int lane = t & 31;

    int beg = __ldg(&ptr[n]);
    int end = beg + __ldg(&cnt[n]);
    float4 acc = make_float4(0.f, 0.f, 0.f, 0.f);

    int e = beg;
    // 8-edge unroll, load/use separated (MLP = 8 feature loads in flight)
    for (; e + 8 <= end; e += 8) {
        int   s[8];
        float w[8];
#pragma unroll
        for (int q = 0; q < 8; q++) s[q] = __ldg(&ci[e + q]);
#pragma unroll
        for (int q = 0; q < 8; q++) w[q] = __ldg(&wv[e + q]);
        uint2 v[8];
#pragma unroll
        for (int q = 0; q < 8; q++)
            v[q] = *(const uint2*)&x[(size_t)s[q] * 64 + lane * 2];
#pragma unroll
        for (int q = 0; q < 8; q++) acc_bf2(acc, v[q], w[q]);
    }
    // 4-edge group
    if (e + 4 <= end) {
        int   s[4];
        float w[4];
#pragma unroll
        for (int q = 0; q < 4; q++) s[q] = __ldg(&ci[e + q]);
#pragma unroll
        for (int q = 0; q < 4; q++) w[q] = __ldg(&wv[e + q]);
        uint2 v[4];
#pragma unroll
        for (int q = 0; q < 4; q++)
            v[q] = *(const uint2*)&x[(size_t)s[q] * 64 + lane * 2];
#pragma unroll
        for (int q = 0; q < 4; q++) acc_bf2(acc, v[q], w[q]);
        e += 4;
    }
    for (; e < end; e++) {
        int s = __ldg(&ci[e]);
        float w0 = __ldg(&wv[e]);
        uint2 v = *(const uint2*)&x[(size_t)s * 64 + lane * 2];
        acc_bf2(acc, v, w0);
    }
    *(float4*)&out[(size_t)n * 128 + lane * 4] = acc;
}

// two bf16 features -> two fp32 outputs; 4-edge unroll (8 loads in flight)
__global__ __launch_bounds__(256) void gather2_kernel(
    const int* __restrict__ ptr, const int* __restrict__ cnt,
    const int* __restrict__ ci, const float* __restrict__ wv,
    const u32* __restrict__ x0, const u32* __restrict__ x1,
    float* __restrict__ o0, float* __restrict__ o1, int N)
{
    int t = blockIdx.x * blockDim.x + threadIdx.x;
    int n = t >> 5;
    if (n >= N) return;
    int lane = t & 31;

    int beg = __ldg(&ptr[n]);
    int end = beg + __ldg(&cnt[n]);
    float4 a0 = make_float4(0.f, 0.f, 0.f, 0.f);
    float4 a1 = a0;

    int e = beg;
    for (; e + 4 <= end; e += 4) {
        int   s[4];
        float w[4];
#pragma unroll
        for (int q = 0; q < 4; q++) s[q] = __ldg(&ci[e + q]);
#pragma unroll
        for (int q = 0; q < 4; q++) w[q] = __ldg(&wv[e + q]);
        uint2 v0[4], v1[4];
#pragma unroll
        for (int q = 0; q < 4; q++) {
            size_t o = (size_t)s[q] * 64 + lane * 2;
            v0[q] = *(const uint2*)&x0[o];
            v1[q] = *(const uint2*)&x1[o];
        }
#pragma unroll
        for (int q = 0; q < 4; q++) {
            acc_bf2(a0, v0[q], w[q]);
            acc_bf2(a1, v1[q], w[q]);
        }
    }
    for (; e < end; e++) {
        int s = __ldg(&ci[e]);
        float w0 = __ldg(&wv[e]);
        size_t o = (size_t)s * 64 + lane * 2;
        uint2 v0 = *(const uint2*)&x0[o];
        uint2 v1 = *(const uint2*)&x1[o];
        acc_bf2(a0, v0, w0);
        acc_bf2(a1, v1, w0);
    }
    size_t od = (size_t)n * 128 + lane * 4;
    *(float4*)&o0[od] = a0;
    *(float4*)&o1[od] = a1;
}

// fp32 features -> fp32 out (word_emb; off critical path)
__global__ __launch_bounds__(256) void gather1f_kernel(
    const int* __restrict__ ptr, const int* __restrict__ cnt,
    const int* __restrict__ ci, const float* __restrict__ wv,
    const float* __restrict__ x, float* __restrict__ out, int N)
{
    int t = blockIdx.x * blockDim.x + threadIdx.x;
    int n = t >> 5;
    if (n >= N) return;
    int lane = t & 31;

    int beg = __ldg(&ptr[n]);
    int end = beg + __ldg(&cnt[n]);
    float4 acc = make_float4(0.f, 0.f, 0.f, 0.f);

    int e = beg;
    for (; e + 4 <= end; e += 4) {
        int s0 = __ldg(&ci[e]),   s1 = __ldg(&ci[e+1]);
        int s2 = __ldg(&ci[e+2]), s3 = __ldg(&ci[e+3]);
        float w0 = __ldg(&wv[e]),   w1 = __ldg(&wv[e+1]);
        float w2 = __ldg(&wv[e+2]), w3 = __ldg(&wv[e+3]);
        float4 v0 = *(const float4*)&x[(size_t)s0 * 128 + lane * 4];
        float4 v1 = *(const float4*)&x[(size_t)s1 * 128 + lane * 4];
        float4 v2 = *(const float4*)&x[(size_t)s2 * 128 + lane * 4];
        float4 v3 = *(const float4*)&x[(size_t)s3 * 128 + lane * 4];
        acc.x = fmaf(w0, v0.x, fmaf(w1, v1.x, fmaf(w2, v2.x, fmaf(w3, v3.x, acc.x))));
        acc.y = fmaf(w0, v0.y, fmaf(w1, v1.y, fmaf(w2, v2.y, fmaf(w3, v3.y, acc.y))));
        acc.z = fmaf(w0, v0.z, fmaf(w1, v1.z, fmaf(w2, v2.z, fmaf(w3, v3.z, acc.z))));
        acc.w = fmaf(w0, v0.w, fmaf(w1, v1.w, fmaf(w2, v2.w, fmaf(w3, v3.w, acc.w))));
    }
    for (; e < end; e++) {
        int s = __ldg(&ci[e]);
        float w0 = __ldg(&wv[e]);
        float4 v = *(const float4*)&x[(size_t)s * 128 + lane * 4];
        acc.x = fmaf(w0, v.x, acc.x);
        acc.y = fmaf(w0, v.y, acc.y);
        acc.z = fmaf(w0, v.z, acc.z);
        acc.w = fmaf(w0, v.w, acc.w);
    }
    *(float4*)&out[(size_t)n * 128 + lane * 4] = acc;
}

// ===========================================================================
// Finalize
// ===========================================================================
__global__ __launch_bounds__(128) void finalize_kernel(
    const float* __restrict__ r0, const float* __restrict__ rA,
    const float* __restrict__ rw, const float* __restrict__ r0s,
    const float* __restrict__ rB, float* __restrict__ out)
{
    const int n = blockIdx.x;
    const int t = threadIdx.x;
    const int lane = t & 31, wid = t >> 5;

    const size_t base = (size_t)n * 128 + t;
    float v0  = r0 [base];
    float vA  = rA [base];
    float vW  = rw [base];
    float v0s = r0s[base];
    float vB  = rB [base];

    float4 sq = make_float4(v0 * v0, vA * vA + vW * vW,
                            v0s * v0s, vB * vB + vW * vW);
#pragma unroll
    for (int o = 16; o; o >>= 1) {
        sq.x += __shfl_xor_sync(0xffffffffu, sq.x, o);
        sq.y += __shfl_xor_sync(0xffffffffu, sq.y, o);
        sq.z += __shfl_xor_sync(0xffffffffu, sq.z, o);
        sq.w += __shfl_xor_sync(0xffffffffu, sq.w, o);
    }
    __shared__ float4 wsum[4];
    if (lane == 0) wsum[wid] = sq;
    __syncthreads();
    float s0  = wsum[0].x + wsum[1].x + wsum[2].x + wsum[3].x;
    float s1  = wsum[0].y + wsum[1].y + wsum[2].y + wsum[3].y;
    float s0s = wsum[0].z + wsum[1].z + wsum[2].z + wsum[3].z;
    float s1s = wsum[0].w + wsum[1].w + wsum[2].w + wsum[3].w;

    const float EPS = 1e-9f;
    float i0  = 1.f / (sqrtf(s0)  + EPS);
    float i1  = 1.f / (sqrtf(s1)  + EPS);
    float i0s = 1.f / (sqrtf(s0s) + EPS);
    float i1s = 1.f / (sqrtf(s1s) + EPS);

    size_t drow = (size_t)n * 384;
    out[drow + t]       = v0 * i0;
    out[drow + 128 + t] = vA * i1;
    out[drow + 256 + t] = vW * i1;

    size_t srow = (size_t)N0_DOCS * 384 + drow;
    out[srow + t]       = v0s * i0s;
    out[srow + 128 + t] = vB * i1s;
    out[srow + 256 + t] = vW * i1s;
}

// ===========================================================================
// Launch (round-12 topology)
// ===========================================================================
extern "C" void kernel_launch(void* const* d_in, const int* in_sizes, int n_in,
                              void* d_out, int out_size)
{
    const float* x1       = (const float*)d_in[0];
    const float* x2       = (const float*)d_in[1];
    const float* word_emb = (const float*)d_in[2];
    const float* W1a = (const float*)d_in[3];
    const float* b1a = (const float*)d_in[4];
    const float* W1b = (const float*)d_in[5];
    const float* b1b = (const float*)d_in[6];
    const float* W2a = (const float*)d_in[7];
    const float* b2a = (const float*)d_in[8];
    const float* W2b = (const float*)d_in[9];
    const float* b2b = (const float*)d_in[10];
    const int*   e11_src = (const int*)d_in[11];
    const int*   e11_dst = (const int*)d_in[12];
    const float* e11_w   = (const float*)d_in[13];
    const int*   e22_src = (const int*)d_in[14];
    const int*   e22_dst = (const int*)d_in[15];
    const float* e22_w   = (const float*)d_in[16];
    const int*   e01_src = (const int*)d_in[17];
    const int*   e01_dst = (const int*)d_in[18];
    const float* e01_w   = (const float*)d_in[19];
    const int*   e02_src = (const int*)d_in[20];
    const int*   e02_dst = (const int*)d_in[21];
    const float* e02_w   = (const float*)d_in[22];

    const int N1  = in_sizes[0] / 256;
    const int N2  = in_sizes[1] / 256;
    const int E11 = in_sizes[11];
    const int E22 = in_sizes[14];
    const int E01 = in_sizes[17];
    const int E02 = in_sizes[20];
    const int Etot = E11 + E22 + E01 + E02;
    const int Ntot = N1 + N2 + 2 * N0_DOCS;
    const int b22 = N1, b01 = N1 + N2, b02 = N1 + N2 + N0_DOCS;

    u32 *l1_1, *l2_1, *l1_2, *l2_2;
    float *h1, *h2, *r0, *r0s, *rA, *rB, *rw;
    cudaGetSymbolAddress((void**)&l1_1, g_l1_1);
    cudaGetSymbolAddress((void**)&l2_1, g_l2_1);
    cudaGetSymbolAddress((void**)&l1_2, g_l1_2);
    cudaGetSymbolAddress((void**)&l2_2, g_l2_2);
    cudaGetSymbolAddress((void**)&h1,   g_h1);
    cudaGetSymbolAddress((void**)&h2,   g_h2);
    cudaGetSymbolAddress((void**)&r0,   g_r0);
    cudaGetSymbolAddress((void**)&r0s,  g_r0s);
    cudaGetSymbolAddress((void**)&rA,   g_rA);
    cudaGetSymbolAddress((void**)&rB,   g_rB);
    cudaGetSymbolAddress((void**)&rw,   g_rw);

    int *cntfc, *ptr, *ci, *bsum;
    float *wv;
    cudaGetSymbolAddress((void**)&cntfc, g_cntfc);
    cudaGetSymbolAddress((void**)&ptr,   g_ptr);
    cudaGetSymbolAddress((void**)&ci,    g_ci);
    cudaGetSymbolAddress((void**)&wv,    g_wv);
    cudaGetSymbolAddress((void**)&bsum,  g_bsum);
    int* cnt = cntfc;
    int* fc  = cntfc + NTOT;

    static cudaStream_t s1 = nullptr, s2 = nullptr, s3 = nullptr;
    static cudaEvent_t ev0 = nullptr, ev1 = nullptr, ev2 = nullptr, ev3 = nullptr;
    static cudaEvent_t ecsr = nullptr;
    if (s1 == nullptr) {
        cudaStreamCreateWithFlags(&s1, cudaStreamNonBlocking);
        cudaStreamCreateWithFlags(&s2, cudaStreamNonBlocking);
        cudaStreamCreateWithFlags(&s3, cudaStreamNonBlocking);
        cudaEventCreateWithFlags(&ev0, cudaEventDisableTiming);
        cudaEventCreateWithFlags(&ev1, cudaEventDisableTiming);
        cudaEventCreateWithFlags(&ev2, cudaEventDisableTiming);
        cudaEventCreateWithFlags(&ev3, cudaEventDisableTiming);
        cudaEventCreateWithFlags(&ecsr, cudaEventDisableTiming);
        cudaFuncSetAttribute(gemm_mma_kernel,
                             cudaFuncAttributeMaxDynamicSharedMemorySize, GEMM_SMEM);
    }

    const unsigned gdoc = (N0_DOCS * 32 + 255) / 256;

    // Fork
    cudaEventRecord(ev0, 0);
    cudaStreamWaitEvent(s1, ev0, 0);
    cudaStreamWaitEvent(s2, ev0, 0);
    cudaStreamWaitEvent(s3, ev0, 0);

    // ---- stream 3: fused CSR build + rw gather ----
    cudaMemsetAsync(cntfc, 0, 2 * NTOT * sizeof(int), s3);
    hist_all_kernel<<<(Etot + 255) / 256, 256, 0, s3>>>(
        e11_dst, e22_dst, e01_dst, e02_dst, E11, E22, E01, E02,
        b22, b01, b02, cnt);
    int nb = (Ntot + SCB - 1) / SCB;
    scan1_kernel<<<nb, SCB, 0, s3>>>(cnt, ptr, bsum, Ntot);
    scan2_kernel<<<1, SCB, 0, s3>>>(bsum, nb);
    scan3_kernel<<<nb, SCB, 0, s3>>>(ptr, bsum, Ntot);
    fill_all_kernel<<<(Etot + 255) / 256, 256, 0, s3>>>(
        e11_src, e11_dst, e11_w, e22_src, e22_dst, e22_w,
        e01_src, e01_dst, e01_w, e02_src, e02_dst, e02_w,
        E11, E22, E01, E02, b22, b01, b02, ptr, fc, ci, wv);
    cudaEventRecord(ecsr, s3);
    gather1f_kernel<<<gdoc, 256, 0, s3>>>(
        ptr + b02, cnt + b02, ci, wv, word_emb, rw, N0_DOCS);
    cudaEventRecord(ev3, s3);

    // ---- stream 1: type-1 pipeline ----
    gemm_mma_kernel<<<(N1 + 127) / 128, 256, GEMM_SMEM, s1>>>(
        x1, W1a, b1a, l1_1, N1, 256);
    cudaStreamWaitEvent(s1, ecsr, 0);
    gather1_kernel<<<(N1 * 32 + 255) / 256, 256, 0, s1>>>(
        ptr, cnt, ci, wv, l1_1, h1, N1);
    gemm_mma_kernel<<<(N1 + 127) / 128, 256, GEMM_SMEM, s1>>>(
        h1, W1b, b1b, l2_1, N1, 128);
    gather2_kernel<<<gdoc, 256, 0, s1>>>(
        ptr + b01, cnt + b01, ci, wv, l2_1, l1_1, r0, r0s, N0_DOCS);
    cudaEventRecord(ev1, s1);

    // ---- stream 2: type-2 pipeline ----
    gemm_mma_kernel<<<(N2 + 127) / 128, 256, GEMM_SMEM, s2>>>(
        x2, W2a, b2a, l1_2, N2, 256);
    cudaStreamWaitEvent(s2, ecsr, 0);
    gather1_kernel<<<(N2 * 32 + 255) / 256, 256, 0, s2>>>(
        ptr + b22, cnt + b22, ci, wv, l1_2, h2, N2);
    gemm_mma_kernel<<<(N2 + 127) / 128, 256, GEMM_SMEM, s2>>>(
        h2, W2b, b2b, l2_2, N2, 128);
    gather2_kernel<<<gdoc, 256, 0, s2>>>(
        ptr + b02, cnt + b02, ci, wv, l2_2, l1_2, rA, rB, N0_DOCS);
    cudaEventRecord(ev2, s2);

    // ---- join + finalize ----
    cudaStreamWaitEvent(0, ev1, 0);
    cudaStreamWaitEvent(0, ev2, 0);
    cudaStreamWaitEvent(0, ev3, 0);
    finalize_kernel<<<N0_DOCS, 128, 0, 0>>>(r0, rA, rw, r0s, rB, (float*)d_out);
}